// round 3
// baseline (speedup 1.0000x reference)
#include <cuda_runtime.h>
#include <math.h>

// Problem constants (fixed by the dataset)
#define BB   8192
#define EE   4
#define KK   16
#define DD   128
// derived
#define EDK  (BB*EE)          // 32768 (b,e) pairs
#define AGG_COLS 512          // E*D

// ---------------- scratch (static device globals; no allocation) -------------
__device__ float g_agg[(size_t)BB * AGG_COLS];   // [B, E*D] gathered means
__device__ float g_V[(size_t)BB * DD];           // emb_end[end] * sigmoid(emb_path[path])
__device__ float g_M[(size_t)AGG_COLS * DD];     // blockdiag(W1) @ W2  -> [512,128]
__device__ float g_c[DD];                        // b2 + b1-folded bias

// ---------------------------------------------------------------------------
// prep_c: c[j] = b2[j] + sum_m b1[m&127] * W2[m,j]
__global__ void k_prep_c(const float* __restrict__ b1,
                         const float* __restrict__ W2,
                         const float* __restrict__ b2) {
    int j = threadIdx.x;            // 128 threads
    float s = b2[j];
    for (int m = 0; m < AGG_COLS; ++m)
        s += b1[m & (DD - 1)] * W2[(size_t)m * DD + j];
    g_c[j] = s;
}

// ---------------------------------------------------------------------------
// prep_M: M[e*128 + i, j] = sum_k W1[i,k] * W2[e*128+k, j]
// grid = 8 blocks (4 e x 2 row-halves of 64), 256 threads, 4x8 microtile
__global__ __launch_bounds__(256) void k_prep_M(const float* __restrict__ W1,
                                                const float* __restrict__ W2) {
    __shared__ float As[16][68];
    __shared__ float Bs[16][128];
    int tid = threadIdx.x;
    int tx = tid & 15, ty = tid >> 4;
    int e  = blockIdx.x >> 1;
    int i0 = (blockIdx.x & 1) * 64;

    const float* A  = W1 + (size_t)i0 * DD;        // 64 x 128, lda=128
    const float* Bm = W2 + (size_t)e * DD * DD;    // 128 x 128, ldb=128

    float acc[4][8];
#pragma unroll
    for (int i = 0; i < 4; i++)
#pragma unroll
        for (int j = 0; j < 8; j++) acc[i][j] = 0.f;

    int am = tid >> 2;      // 0..63  (A-tile row)
    int af = tid & 3;       // float4 index within 16-wide k-slab

    for (int kc = 0; kc < DD; kc += 16) {
        __syncthreads();
        float4 av = *(const float4*)(A + (size_t)am * DD + kc + af * 4);
        As[af * 4 + 0][am] = av.x;
        As[af * 4 + 1][am] = av.y;
        As[af * 4 + 2][am] = av.z;
        As[af * 4 + 3][am] = av.w;
#pragma unroll
        for (int it = 0; it < 2; it++) {
            int idx = tid + it * 256;
            int br = idx >> 5, bc = idx & 31;
            *(float4*)&Bs[br][bc * 4] =
                *(const float4*)(Bm + (size_t)(kc + br) * DD + bc * 4);
        }
        __syncthreads();
#pragma unroll
        for (int kk = 0; kk < 16; kk++) {
            float a[4], b[8];
            *(float4*)a       = *(float4*)&As[kk][ty * 4];
            *(float4*)b       = *(float4*)&Bs[kk][tx * 8];
            *(float4*)(b + 4) = *(float4*)&Bs[kk][tx * 8 + 4];
#pragma unroll
            for (int i = 0; i < 4; i++)
#pragma unroll
                for (int j = 0; j < 8; j++) acc[i][j] += a[i] * b[j];
        }
    }
#pragma unroll
    for (int i = 0; i < 4; i++) {
        int row = e * DD + i0 + ty * 4 + i;
        float4 lo = make_float4(acc[i][0], acc[i][1], acc[i][2], acc[i][3]);
        float4 hi = make_float4(acc[i][4], acc[i][5], acc[i][6], acc[i][7]);
        *(float4*)(g_M + (size_t)row * DD + tx * 8)     = lo;
        *(float4*)(g_M + (size_t)row * DD + tx * 8 + 4) = hi;
    }
}

// ---------------------------------------------------------------------------
// V[b,j] = emb_end[end_node[b], j] * sigmoid(emb_path[path[b], j])
// one warp per b; 1024 blocks x 256 threads
__global__ __launch_bounds__(256) void k_V(const int* __restrict__ end_node,
                                           const int* __restrict__ path,
                                           const float* __restrict__ emb_end,
                                           const float* __restrict__ emb_path) {
    int w    = (blockIdx.x * 256 + threadIdx.x) >> 5;  // 0..8191
    int lane = threadIdx.x & 31;
    int en = __ldg(end_node + w);
    int pa = __ldg(path + w);
    float4 ev = *(const float4*)(emb_end  + (size_t)en * DD + lane * 4);
    float4 pv = *(const float4*)(emb_path + (size_t)pa * DD + lane * 4);
    float4 r;
    r.x = ev.x / (1.f + expf(-pv.x));
    r.y = ev.y / (1.f + expf(-pv.y));
    r.z = ev.z / (1.f + expf(-pv.z));
    r.w = ev.w / (1.f + expf(-pv.w));
    *(float4*)(g_V + (size_t)w * DD + lane * 4) = r;
}

// ---------------------------------------------------------------------------
// gather+mean: one warp per (b,e). agg[b, e*128 + c] = mean_k emb_start[nb[b,e,k], c]
// 4096 blocks x 256 threads (8 warps)
__global__ __launch_bounds__(256) void k_gather(const int* __restrict__ nb,
                                                const float* __restrict__ emb) {
    int w    = (blockIdx.x * 256 + threadIdx.x) >> 5;  // 0..32767
    int lane = threadIdx.x & 31;

    int ids[KK];
    const int* ip = nb + (size_t)w * KK;
#pragma unroll
    for (int k = 0; k < KK; k++) ids[k] = __ldg(ip + k);

    float4 acc = make_float4(0.f, 0.f, 0.f, 0.f);
#pragma unroll
    for (int k = 0; k < KK; k++) {
        const float4 v = *(const float4*)(emb + (size_t)ids[k] * DD + lane * 4);
        acc.x += v.x; acc.y += v.y; acc.z += v.z; acc.w += v.w;
    }
    const float inv = 1.f / (float)KK;
    acc.x *= inv; acc.y *= inv; acc.z *= inv; acc.w *= inv;
    *(float4*)(g_agg + (size_t)w * DD + lane * 4) = acc;   // w*128 == b*512 + e*128
}

// ---------------------------------------------------------------------------
// fused GEMM + epilogue:
//   s[b,:] = agg[b,:] @ M + c ;  out[b] = sigmoid( dot(s[b,:], V[b,:]) )
// tile: 64 rows x 128 cols, K=512, 256 threads, 4x8 microtile. grid = 128.
__global__ __launch_bounds__(256) void k_gemm(float* __restrict__ out) {
    __shared__ float As[16][68];
    __shared__ float Bs[16][128];
    int tid = threadIdx.x;
    int tx = tid & 15, ty = tid >> 4;
    int row0 = blockIdx.x * 64;

    float acc[4][8];
#pragma unroll
    for (int i = 0; i < 4; i++)
#pragma unroll
        for (int j = 0; j < 8; j++) acc[i][j] = 0.f;

    float cb[8];
#pragma unroll
    for (int j = 0; j < 8; j++) cb[j] = g_c[tx * 8 + j];

    int am = tid >> 2;
    int af = tid & 3;
    const float* Aptr = g_agg + (size_t)(row0 + am) * AGG_COLS + af * 4;

    for (int kc = 0; kc < AGG_COLS; kc += 16) {
        __syncthreads();
        float4 av = *(const float4*)(Aptr + kc);
        As[af * 4 + 0][am] = av.x;
        As[af * 4 + 1][am] = av.y;
        As[af * 4 + 2][am] = av.z;
        As[af * 4 + 3][am] = av.w;
#pragma unroll
        for (int it = 0; it < 2; it++) {
            int idx = tid + it * 256;
            int br = idx >> 5, bc = idx & 31;
            *(float4*)&Bs[br][bc * 4] =
                *(const float4*)(g_M + (size_t)(kc + br) * DD + bc * 4);
        }
        __syncthreads();
#pragma unroll
        for (int kk = 0; kk < 16; kk++) {
            float a[4], b[8];
            *(float4*)a       = *(float4*)&As[kk][ty * 4];
            *(float4*)b       = *(float4*)&Bs[kk][tx * 8];
            *(float4*)(b + 4) = *(float4*)&Bs[kk][tx * 8 + 4];
#pragma unroll
            for (int i = 0; i < 4; i++)
#pragma unroll
                for (int j = 0; j < 8; j++) acc[i][j] += a[i] * b[j];
        }
    }

    // epilogue: per-row dot with V, reduce over the 16 tx threads, sigmoid
    float part[4];
#pragma unroll
    for (int i = 0; i < 4; i++) {
        int b = row0 + ty * 4 + i;
        float4 v0 = *(const float4*)(g_V + (size_t)b * DD + tx * 8);
        float4 v1 = *(const float4*)(g_V + (size_t)b * DD + tx * 8 + 4);
        float p = 0.f;
        p += (acc[i][0] + cb[0]) * v0.x;
        p += (acc[i][1] + cb[1]) * v0.y;
        p += (acc[i][2] + cb[2]) * v0.z;
        p += (acc[i][3] + cb[3]) * v0.w;
        p += (acc[i][4] + cb[4]) * v1.x;
        p += (acc[i][5] + cb[5]) * v1.y;
        p += (acc[i][6] + cb[6]) * v1.z;
        p += (acc[i][7] + cb[7]) * v1.w;
        part[i] = p;
    }
#pragma unroll
    for (int off = 8; off > 0; off >>= 1) {
#pragma unroll
        for (int i = 0; i < 4; i++)
            part[i] += __shfl_xor_sync(0xffffffffu, part[i], off);
    }
    if (tx == 0) {
#pragma unroll
        for (int i = 0; i < 4; i++) {
            int b = row0 + ty * 4 + i;
            out[b] = 1.f / (1.f + expf(-part[i]));
        }
    }
}

// ---------------------------------------------------------------------------
extern "C" void kernel_launch(void* const* d_in, const int* in_sizes, int n_in,
                              void* d_out, int out_size) {
    const int*   neighbors = (const int*)  d_in[0];
    const int*   end_node  = (const int*)  d_in[1];
    const int*   path      = (const int*)  d_in[2];
    const float* emb_start = (const float*)d_in[3];
    const float* emb_end   = (const float*)d_in[4];
    const float* emb_path  = (const float*)d_in[5];
    const float* W1        = (const float*)d_in[6];
    const float* b1        = (const float*)d_in[7];
    const float* W2        = (const float*)d_in[8];
    const float* b2        = (const float*)d_in[9];
    float*       out       = (float*)d_out;

    k_prep_M<<<8, 256>>>(W1, W2);
    k_prep_c<<<1, 128>>>(b1, W2, b2);
    k_V<<<BB / 8, 256>>>(end_node, path, emb_end, emb_path);
    k_gather<<<EDK / 8, 256>>>(neighbors, emb_start);
    k_gemm<<<BB / 64, 256>>>(out);
}

// round 4
// speedup vs baseline: 1.4921x; 1.4921x over previous
#include <cuda_runtime.h>
#include <cuda_bf16.h>
#include <math.h>

#define BB   8192
#define EE   4
#define KK   16
#define DD   128
#define EDK  (BB*EE)          // 32768 (b,e) pairs
#define AGG_COLS 512          // E*D

// ---------------- scratch (static device globals; no allocation) -------------
__device__ __nv_bfloat16 g_aggh[(size_t)BB * AGG_COLS];  // [B, 512] bf16 means
__device__ float         g_V[(size_t)BB * DD];           // emb_end[end]*sigmoid(emb_path[path])
__device__ __nv_bfloat16 g_Mh[(size_t)AGG_COLS * DD];    // blockdiag(W1)@W2 [512,128] bf16
__device__ float         g_c[DD];                        // b2 + b1-folded bias

// ---------------------------------------------------------------------------
__global__ void k_prep_c(const float* __restrict__ b1,
                         const float* __restrict__ W2,
                         const float* __restrict__ b2) {
    int j = threadIdx.x;            // 128 threads
    float s = b2[j];
    for (int m = 0; m < AGG_COLS; ++m)
        s += b1[m & (DD - 1)] * W2[(size_t)m * DD + j];
    g_c[j] = s;
}

// ---------------------------------------------------------------------------
// prep_M: M[e*128+i, j] = sum_k W1[i,k] * W2[e*128+k, j]  -> bf16
__global__ __launch_bounds__(256) void k_prep_M(const float* __restrict__ W1,
                                                const float* __restrict__ W2) {
    __shared__ float As[16][68];
    __shared__ float Bs[16][128];
    int tid = threadIdx.x;
    int tx = tid & 15, ty = tid >> 4;
    int e  = blockIdx.x >> 1;
    int i0 = (blockIdx.x & 1) * 64;

    const float* A  = W1 + (size_t)i0 * DD;
    const float* Bm = W2 + (size_t)e * DD * DD;

    float acc[4][8];
#pragma unroll
    for (int i = 0; i < 4; i++)
#pragma unroll
        for (int j = 0; j < 8; j++) acc[i][j] = 0.f;

    int am = tid >> 2;
    int af = tid & 3;

    for (int kc = 0; kc < DD; kc += 16) {
        __syncthreads();
        float4 av = *(const float4*)(A + (size_t)am * DD + kc + af * 4);
        As[af * 4 + 0][am] = av.x;
        As[af * 4 + 1][am] = av.y;
        As[af * 4 + 2][am] = av.z;
        As[af * 4 + 3][am] = av.w;
#pragma unroll
        for (int it = 0; it < 2; it++) {
            int idx = tid + it * 256;
            int br = idx >> 5, bc = idx & 31;
            *(float4*)&Bs[br][bc * 4] =
                *(const float4*)(Bm + (size_t)(kc + br) * DD + bc * 4);
        }
        __syncthreads();
#pragma unroll
        for (int kk = 0; kk < 16; kk++) {
            float a[4], b[8];
            *(float4*)a       = *(float4*)&As[kk][ty * 4];
            *(float4*)b       = *(float4*)&Bs[kk][tx * 8];
            *(float4*)(b + 4) = *(float4*)&Bs[kk][tx * 8 + 4];
#pragma unroll
            for (int i = 0; i < 4; i++)
#pragma unroll
                for (int j = 0; j < 8; j++) acc[i][j] += a[i] * b[j];
        }
    }
#pragma unroll
    for (int i = 0; i < 4; i++) {
        int row = e * DD + i0 + ty * 4 + i;
        __nv_bfloat162 h0 = __floats2bfloat162_rn(acc[i][0], acc[i][1]);
        __nv_bfloat162 h1 = __floats2bfloat162_rn(acc[i][2], acc[i][3]);
        __nv_bfloat162 h2 = __floats2bfloat162_rn(acc[i][4], acc[i][5]);
        __nv_bfloat162 h3 = __floats2bfloat162_rn(acc[i][6], acc[i][7]);
        uint4 pk;
        pk.x = *(unsigned*)&h0; pk.y = *(unsigned*)&h1;
        pk.z = *(unsigned*)&h2; pk.w = *(unsigned*)&h3;
        *(uint4*)(g_Mh + (size_t)row * DD + tx * 8) = pk;
    }
}

// ---------------------------------------------------------------------------
// V[b,j] = emb_end[end_node[b], j] * sigmoid(emb_path[path[b], j])
__global__ __launch_bounds__(256) void k_V(const int* __restrict__ end_node,
                                           const int* __restrict__ path,
                                           const float* __restrict__ emb_end,
                                           const float* __restrict__ emb_path) {
    int w    = (blockIdx.x * 256 + threadIdx.x) >> 5;
    int lane = threadIdx.x & 31;
    int en = __ldg(end_node + w);
    int pa = __ldg(path + w);
    float4 ev = *(const float4*)(emb_end  + (size_t)en * DD + lane * 4);
    float4 pv = *(const float4*)(emb_path + (size_t)pa * DD + lane * 4);
    float4 r;
    r.x = ev.x / (1.f + expf(-pv.x));
    r.y = ev.y / (1.f + expf(-pv.y));
    r.z = ev.z / (1.f + expf(-pv.z));
    r.w = ev.w / (1.f + expf(-pv.w));
    *(float4*)(g_V + (size_t)w * DD + lane * 4) = r;
}

// ---------------------------------------------------------------------------
// gather+mean -> bf16: one warp per (b,e)
__global__ __launch_bounds__(256) void k_gather(const int* __restrict__ nb,
                                                const float* __restrict__ emb) {
    int w    = (blockIdx.x * 256 + threadIdx.x) >> 5;
    int lane = threadIdx.x & 31;

    int ids[KK];
    const int* ip = nb + (size_t)w * KK;
#pragma unroll
    for (int k = 0; k < KK; k++) ids[k] = __ldg(ip + k);

    float4 acc = make_float4(0.f, 0.f, 0.f, 0.f);
#pragma unroll
    for (int k = 0; k < KK; k++) {
        const float4 v = *(const float4*)(emb + (size_t)ids[k] * DD + lane * 4);
        acc.x += v.x; acc.y += v.y; acc.z += v.z; acc.w += v.w;
    }
    const float inv = 1.f / (float)KK;
    __nv_bfloat162 h0 = __floats2bfloat162_rn(acc.x * inv, acc.y * inv);
    __nv_bfloat162 h1 = __floats2bfloat162_rn(acc.z * inv, acc.w * inv);
    uint2 pk; pk.x = *(unsigned*)&h0; pk.y = *(unsigned*)&h1;
    *(uint2*)(g_aggh + (size_t)w * DD + lane * 4) = pk;   // w*128 == b*512 + e*128
}

// ---------------------------------------------------------------------------
// Tensor-core GEMM + fused epilogue.
//   C[64x128] tile = A(bf16)[64x512] @ M(bf16)[512x128]; out[b]=sigmoid(dot(C[b]+c, V[b]))
// 256 threads (8 warps: 4 row-groups x 2 col-halves). Whole M in smem (139KB),
// A staged per 32-k chunk with register-prefetch double buffer.
#define B_LD  136                       // padded bf16 stride for M in smem
#define A_LD  40                        // padded bf16 stride for A chunk
#define BS_ELEMS (AGG_COLS * B_LD)      // 69632
#define AS_ELEMS (2 * 64 * A_LD)        // 5120
#define GEMM_SMEM ((BS_ELEMS + AS_ELEMS) * 2 + 64 * 2 * 4)

__device__ __forceinline__ unsigned s2u(const void* p) {
    return (unsigned)__cvta_generic_to_shared(p);
}

__global__ __launch_bounds__(256) void k_gemm_tc(float* __restrict__ out) {
    extern __shared__ char sm_raw[];
    __nv_bfloat16* Bs = (__nv_bfloat16*)sm_raw;
    __nv_bfloat16* As = Bs + BS_ELEMS;
    float (*epi)[2]   = (float (*)[2])(As + AS_ELEMS);

    int tid  = threadIdx.x;
    int wid  = tid >> 5;
    int lane = tid & 31;
    int row0 = blockIdx.x * 64;

    // ---- load whole M into smem (padded) ----
    {
        const uint4* src = (const uint4*)g_Mh;   // 8192 uint4
#pragma unroll
        for (int it = 0; it < 32; it++) {
            int idx = tid + it * 256;            // 0..8191
            int r = idx >> 4, seg = idx & 15;    // row 0..511, 8-bf16 seg
            *(uint4*)(Bs + r * B_LD + seg * 8) = src[idx];
        }
    }

    // ---- stage A chunk 0 ----
    int ar  = tid >> 2;        // 0..63
    int asg = tid & 3;         // 0..3 (8-bf16 segment)
    const uint4* Agl = (const uint4*)(g_aggh + (size_t)(row0 + ar) * AGG_COLS + asg * 8);
    // chunk c covers cols [32c, 32c+32): uint4 index = c*4 + asg? No: per row, 512 bf16
    // = 64 uint4; chunk c segs are at uint4 offset c*4 + asg.
    {
        uint4 v = Agl[0 * 4 + 0];  // placeholder overwritten below
        v = *((const uint4*)(g_aggh + (size_t)(row0 + ar) * AGG_COLS) + asg);
        *(uint4*)(As + 0 * (64 * A_LD) + ar * A_LD + asg * 8) = v;
    }

    float acc[8][4];
#pragma unroll
    for (int f = 0; f < 8; f++)
#pragma unroll
        for (int j = 0; j < 4; j++) acc[f][j] = 0.f;

    int mrow_base = 16 * (wid & 3);
    int nb        = (wid >> 2) * 64;
    int li = lane & 7, lq = lane >> 3;
    // A ldmatrix lane address components
    int a_row = mrow_base + li + ((lq & 1) << 3);
    int a_kof = (lq >> 1) << 3;
    // B ldmatrix lane address components
    int b_kof = li + ((lq & 1) << 3);
    int b_nof = nb + ((lq >> 1) << 3);

    const uint4* ArowBase = (const uint4*)(g_aggh + (size_t)(row0 + ar) * AGG_COLS);

    for (int chunk = 0; chunk < 16; chunk++) {
        int cur = chunk & 1;
        __syncthreads();
        uint4 nxt;
        if (chunk < 15) nxt = ArowBase[(chunk + 1) * 4 + asg];

        __nv_bfloat16* Ab = As + cur * (64 * A_LD);
#pragma unroll
        for (int ks = 0; ks < 2; ks++) {          // two k16 steps per chunk
            int klocal = ks * 16;
            unsigned a0, a1, a2, a3;
            unsigned aaddr = s2u(Ab + a_row * A_LD + klocal + a_kof);
            asm volatile("ldmatrix.sync.aligned.m8n8.x4.shared.b16 {%0,%1,%2,%3}, [%4];"
                         : "=r"(a0), "=r"(a1), "=r"(a2), "=r"(a3) : "r"(aaddr));
            int kg = chunk * 32 + klocal;
#pragma unroll
            for (int f2 = 0; f2 < 4; f2++) {
                unsigned t0, t1, t2, t3;
                unsigned baddr = s2u(Bs + (kg + b_kof) * B_LD + b_nof + f2 * 16);
                asm volatile("ldmatrix.sync.aligned.m8n8.x4.trans.shared.b16 {%0,%1,%2,%3}, [%4];"
                             : "=r"(t0), "=r"(t1), "=r"(t2), "=r"(t3) : "r"(baddr));
                int f = f2 * 2;
                asm volatile("mma.sync.aligned.m16n8k16.row.col.f32.bf16.bf16.f32 "
                             "{%0,%1,%2,%3}, {%4,%5,%6,%7}, {%8,%9}, {%0,%1,%2,%3};"
                             : "+f"(acc[f][0]), "+f"(acc[f][1]), "+f"(acc[f][2]), "+f"(acc[f][3])
                             : "r"(a0), "r"(a1), "r"(a2), "r"(a3), "r"(t0), "r"(t1));
                asm volatile("mma.sync.aligned.m16n8k16.row.col.f32.bf16.bf16.f32 "
                             "{%0,%1,%2,%3}, {%4,%5,%6,%7}, {%8,%9}, {%0,%1,%2,%3};"
                             : "+f"(acc[f+1][0]), "+f"(acc[f+1][1]), "+f"(acc[f+1][2]), "+f"(acc[f+1][3])
                             : "r"(a0), "r"(a1), "r"(a2), "r"(a3), "r"(t2), "r"(t3));
            }
        }
        if (chunk < 15)
            *(uint4*)(As + (1 - cur) * (64 * A_LD) + ar * A_LD + asg * 8) = nxt;
    }

    // ---- fused epilogue: dot with V, cross-lane + cross-warp reduce, sigmoid ----
    int q = lane & 3, g = lane >> 2;
    int r = mrow_base + g;            // rows r (c0,c1) and r+8 (c2,c3)
    int brow0 = row0 + r;
    float p0 = 0.f, p1 = 0.f;
#pragma unroll
    for (int f = 0; f < 8; f++) {
        int n = nb + f * 8 + 2 * q;
        float2 cb = *(const float2*)&g_c[n];
        float2 v0 = *(const float2*)&g_V[(size_t)brow0 * DD + n];
        float2 v1 = *(const float2*)&g_V[(size_t)(brow0 + 8) * DD + n];
        p0 += (acc[f][0] + cb.x) * v0.x + (acc[f][1] + cb.y) * v0.y;
        p1 += (acc[f][2] + cb.x) * v1.x + (acc[f][3] + cb.y) * v1.y;
    }
    p0 += __shfl_xor_sync(0xffffffffu, p0, 1);
    p0 += __shfl_xor_sync(0xffffffffu, p0, 2);
    p1 += __shfl_xor_sync(0xffffffffu, p1, 1);
    p1 += __shfl_xor_sync(0xffffffffu, p1, 2);
    if (q == 0) {
        epi[r][wid >> 2]     = p0;
        epi[r + 8][wid >> 2] = p1;
    }
    __syncthreads();
    if (tid < 64) {
        float x = epi[tid][0] + epi[tid][1];
        out[row0 + tid] = 1.f / (1.f + expf(-x));
    }
}

// ---------------------------------------------------------------------------
extern "C" void kernel_launch(void* const* d_in, const int* in_sizes, int n_in,
                              void* d_out, int out_size) {
    const int*   neighbors = (const int*)  d_in[0];
    const int*   end_node  = (const int*)  d_in[1];
    const int*   path      = (const int*)  d_in[2];
    const float* emb_start = (const float*)d_in[3];
    const float* emb_end   = (const float*)d_in[4];
    const float* emb_path  = (const float*)d_in[5];
    const float* W1        = (const float*)d_in[6];
    const float* b1        = (const float*)d_in[7];
    const float* W2        = (const float*)d_in[8];
    const float* b2        = (const float*)d_in[9];
    float*       out       = (float*)d_out;

    cudaFuncSetAttribute(k_gemm_tc, cudaFuncAttributeMaxDynamicSharedMemorySize,
                         GEMM_SMEM);

    k_prep_M<<<8, 256>>>(W1, W2);
    k_prep_c<<<1, 128>>>(b1, W2, b2);
    k_V<<<BB / 8, 256>>>(end_node, path, emb_end, emb_path);
    k_gather<<<EDK / 8, 256>>>(neighbors, emb_start);
    k_gemm_tc<<<BB / 64, 256, GEMM_SMEM>>>(out);
}

// round 6
// speedup vs baseline: 1.8407x; 1.2337x over previous
#include <cuda_runtime.h>
#include <cuda_bf16.h>
#include <math.h>

#define BB   8192
#define EE   4
#define KK   16
#define DD   128
#define AGG_COLS 512          // E*D

// ---------------- scratch (static device globals; no allocation) -------------
__device__ float         g_V[(size_t)BB * DD];           // emb_end[end]*sigmoid(emb_path[path])
__device__ __nv_bfloat16 g_Mh[(size_t)AGG_COLS * DD];    // blockdiag(W1)@W2 [512,128] bf16
__device__ float         g_c[DD];                        // b2 + b1-folded bias

__device__ __forceinline__ unsigned s2u(const void* p) {
    return (unsigned)__cvta_generic_to_shared(p);
}

// ---------------------------------------------------------------------------
// k_prep: one grid, three roles.
//   blocks 0..31   : M[e*128+i, j] = sum_k W1[i,k]*W2[e*128+k, j]  (16x128 tile each)
//   block  32      : c[j] = b2[j] + sum_m b1[m&127]*W2[m,j]
//   blocks 33..160 : V[b,:] = emb_end[end[b],:] * sigmoid(emb_path[path[b],:])
__global__ __launch_bounds__(256) void k_prep(const float* __restrict__ W1,
                                              const float* __restrict__ W2,
                                              const float* __restrict__ b1,
                                              const float* __restrict__ b2,
                                              const int*   __restrict__ end_node,
                                              const int*   __restrict__ path,
                                              const float* __restrict__ emb_end,
                                              const float* __restrict__ emb_path) {
    __shared__ float smA[16][17];
    __shared__ float smB[16][132];
    __shared__ float red[256];
    int bid = blockIdx.x;
    int tid = threadIdx.x;

    if (bid < 32) {
        // ---- M tile: e = bid>>3, rows [i0, i0+16), all 128 cols ----
        int e  = bid >> 3;
        int i0 = (bid & 7) * 16;
        int tx = tid & 15, ty = tid >> 4;
        const float* Bm = W2 + (size_t)e * DD * DD;

        float acc[8];
#pragma unroll
        for (int j = 0; j < 8; j++) acc[j] = 0.f;

        int la_i = tid >> 4, la_k = tid & 15;   // A loader: row, k

        for (int kc = 0; kc < DD; kc += 16) {
            __syncthreads();
            smA[la_k][la_i] = W1[(size_t)(i0 + la_i) * DD + kc + la_k];
#pragma unroll
            for (int it = 0; it < 2; it++) {
                int idx = tid + it * 256;
                int br = idx >> 5, bc = idx & 31;
                *(float4*)&smB[br][bc * 4] =
                    *(const float4*)(Bm + (size_t)(kc + br) * DD + bc * 4);
            }
            __syncthreads();
#pragma unroll
            for (int kk = 0; kk < 16; kk++) {
                float a = smA[kk][ty];
                float4 v0 = *(float4*)&smB[kk][tx * 8];
                float4 v1 = *(float4*)&smB[kk][tx * 8 + 4];
                acc[0] += a * v0.x; acc[1] += a * v0.y;
                acc[2] += a * v0.z; acc[3] += a * v0.w;
                acc[4] += a * v1.x; acc[5] += a * v1.y;
                acc[6] += a * v1.z; acc[7] += a * v1.w;
            }
        }
        int row = e * DD + i0 + ty;
        __nv_bfloat162 h0 = __floats2bfloat162_rn(acc[0], acc[1]);
        __nv_bfloat162 h1 = __floats2bfloat162_rn(acc[2], acc[3]);
        __nv_bfloat162 h2 = __floats2bfloat162_rn(acc[4], acc[5]);
        __nv_bfloat162 h3 = __floats2bfloat162_rn(acc[6], acc[7]);
        uint4 pk;
        pk.x = *(unsigned*)&h0; pk.y = *(unsigned*)&h1;
        pk.z = *(unsigned*)&h2; pk.w = *(unsigned*)&h3;
        *(uint4*)(g_Mh + (size_t)row * DD + tx * 8) = pk;
    } else if (bid == 32) {
        // ---- c ----
        int j = tid & 127, h = tid >> 7;        // h in {0,1}, 256 m each
        float s = (h == 0) ? b2[j] : 0.f;
#pragma unroll 16
        for (int mm = 0; mm < 256; mm++) {
            int m = h * 256 + mm;
            s += b1[m & (DD - 1)] * W2[(size_t)m * DD + j];
        }
        red[tid] = s;
        __syncthreads();
        if (tid < 128) g_c[tid] = red[tid] + red[tid + 128];
    } else {
        // ---- V: 128 CTAs x 8 warps x 8 rows ----
        int v    = bid - 33;
        int wrp  = v * 8 + (tid >> 5);          // 0..1023
        int lane = tid & 31;
#pragma unroll
        for (int i = 0; i < 8; i++) {
            int b  = wrp * 8 + i;
            int en = __ldg(end_node + b);
            int pa = __ldg(path + b);
            float4 ev = *(const float4*)(emb_end  + (size_t)en * DD + lane * 4);
            float4 pv = *(const float4*)(emb_path + (size_t)pa * DD + lane * 4);
            float4 r;
            r.x = ev.x / (1.f + expf(-pv.x));
            r.y = ev.y / (1.f + expf(-pv.y));
            r.z = ev.z / (1.f + expf(-pv.z));
            r.w = ev.w / (1.f + expf(-pv.w));
            *(float4*)(g_V + (size_t)b * DD + lane * 4) = r;
        }
    }
}

// ---------------------------------------------------------------------------
// Fused gather + tensor-core GEMM + epilogue.
//   CTA handles 64 batch rows: gathers 64x4x16 neighbor rows -> bf16 agg in smem,
//   multiplies by resident M (512x128 bf16 in smem), dot with V, sigmoid.
// 512 threads = 16 warps (4 row-groups x 4 col-groups of n32).
#define B_LD  136
#define A_LD  520
#define BS_ELEMS (AGG_COLS * B_LD)              // 69632 bf16
#define AS_ELEMS (64 * A_LD)                    // 33280 bf16
#define FUSED_SMEM ((BS_ELEMS + AS_ELEMS) * 2 + 64 * 4 * 4)

__global__ __launch_bounds__(512) void k_fused(const int*   __restrict__ nb,
                                               const float* __restrict__ emb,
                                               float*       __restrict__ out) {
    extern __shared__ char sm_raw[];
    __nv_bfloat16* Bs = (__nv_bfloat16*)sm_raw;
    __nv_bfloat16* As = Bs + BS_ELEMS;
    float (*epi)[4]   = (float (*)[4])(As + AS_ELEMS);

    int tid  = threadIdx.x;
    int wid  = tid >> 5;        // 0..15
    int lane = tid & 31;
    int row0 = blockIdx.x * 64;

    // ---- load whole M into smem (8192 uint4 over 512 threads) ----
    {
        const uint4* src = (const uint4*)g_Mh;
#pragma unroll
        for (int it = 0; it < 16; it++) {
            int idx = tid + it * 512;           // 0..8191
            int r = idx >> 4, seg = idx & 15;
            *(uint4*)(Bs + r * B_LD + seg * 8) = src[idx];
        }
    }

    // ---- gather: each warp handles 16 (b,e) pairs ----
#pragma unroll 1
    for (int i = 0; i < 16; i++) {
        int p  = wid * 16 + i;                  // 0..255
        int bl = p >> 2, e = p & 3;
        const int* ip = nb + ((size_t)(row0 + bl) * 4 + e) * KK;
        int4 id0 = __ldg((const int4*)ip + 0);
        int4 id1 = __ldg((const int4*)ip + 1);
        int4 id2 = __ldg((const int4*)ip + 2);
        int4 id3 = __ldg((const int4*)ip + 3);

        const float* base = emb + lane * 4;
        float4 v[16];
        v[0]  = *(const float4*)(base + (size_t)id0.x * DD);
        v[1]  = *(const float4*)(base + (size_t)id0.y * DD);
        v[2]  = *(const float4*)(base + (size_t)id0.z * DD);
        v[3]  = *(const float4*)(base + (size_t)id0.w * DD);
        v[4]  = *(const float4*)(base + (size_t)id1.x * DD);
        v[5]  = *(const float4*)(base + (size_t)id1.y * DD);
        v[6]  = *(const float4*)(base + (size_t)id1.z * DD);
        v[7]  = *(const float4*)(base + (size_t)id1.w * DD);
        v[8]  = *(const float4*)(base + (size_t)id2.x * DD);
        v[9]  = *(const float4*)(base + (size_t)id2.y * DD);
        v[10] = *(const float4*)(base + (size_t)id2.z * DD);
        v[11] = *(const float4*)(base + (size_t)id2.w * DD);
        v[12] = *(const float4*)(base + (size_t)id3.x * DD);
        v[13] = *(const float4*)(base + (size_t)id3.y * DD);
        v[14] = *(const float4*)(base + (size_t)id3.z * DD);
        v[15] = *(const float4*)(base + (size_t)id3.w * DD);

        float4 s0 = make_float4(0.f, 0.f, 0.f, 0.f), s1 = s0;
#pragma unroll
        for (int k = 0; k < 8; k++) {
            s0.x += v[k].x; s0.y += v[k].y; s0.z += v[k].z; s0.w += v[k].w;
        }
#pragma unroll
        for (int k = 8; k < 16; k++) {
            s1.x += v[k].x; s1.y += v[k].y; s1.z += v[k].z; s1.w += v[k].w;
        }
        const float inv = 1.f / (float)KK;
        __nv_bfloat162 h0 = __floats2bfloat162_rn((s0.x + s1.x) * inv, (s0.y + s1.y) * inv);
        __nv_bfloat162 h1 = __floats2bfloat162_rn((s0.z + s1.z) * inv, (s0.w + s1.w) * inv);
        uint2 pk; pk.x = *(unsigned*)&h0; pk.y = *(unsigned*)&h1;
        *(uint2*)(As + bl * A_LD + e * DD + lane * 4) = pk;
    }
    __syncthreads();

    // ---- tensor-core GEMM: C[64x128] = A[64x512] @ M[512x128] ----
    int mrow_base = 16 * (wid & 3);
    int nbase     = (wid >> 2) * 32;
    int li = lane & 7, lq = lane >> 3;
    int a_row = mrow_base + li + ((lq & 1) << 3);
    int a_kof = (lq >> 1) << 3;
    int b_kof = li + ((lq & 1) << 3);
    int b_nof = nbase + ((lq >> 1) << 3);

    float acc[4][4];
#pragma unroll
    for (int f = 0; f < 4; f++)
#pragma unroll
        for (int j = 0; j < 4; j++) acc[f][j] = 0.f;

#pragma unroll 4
    for (int ks = 0; ks < 32; ks++) {
        int k = ks * 16;
        unsigned a0, a1, a2, a3;
        unsigned aaddr = s2u(As + a_row * A_LD + k + a_kof);
        asm volatile("ldmatrix.sync.aligned.m8n8.x4.shared.b16 {%0,%1,%2,%3}, [%4];"
                     : "=r"(a0), "=r"(a1), "=r"(a2), "=r"(a3) : "r"(aaddr));
#pragma unroll
        for (int f2 = 0; f2 < 2; f2++) {
            unsigned t0, t1, t2, t3;
            unsigned baddr = s2u(Bs + (k + b_kof) * B_LD + b_nof + f2 * 16);
            asm volatile("ldmatrix.sync.aligned.m8n8.x4.trans.shared.b16 {%0,%1,%2,%3}, [%4];"
                         : "=r"(t0), "=r"(t1), "=r"(t2), "=r"(t3) : "r"(baddr));
            int f = f2 * 2;
            asm volatile("mma.sync.aligned.m16n8k16.row.col.f32.bf16.bf16.f32 "
                         "{%0,%1,%2,%3}, {%4,%5,%6,%7}, {%8,%9}, {%0,%1,%2,%3};"
                         : "+f"(acc[f][0]), "+f"(acc[f][1]), "+f"(acc[f][2]), "+f"(acc[f][3])
                         : "r"(a0), "r"(a1), "r"(a2), "r"(a3), "r"(t0), "r"(t1));
            asm volatile("mma.sync.aligned.m16n8k16.row.col.f32.bf16.bf16.f32 "
                         "{%0,%1,%2,%3}, {%4,%5,%6,%7}, {%8,%9}, {%0,%1,%2,%3};"
                         : "+f"(acc[f+1][0]), "+f"(acc[f+1][1]), "+f"(acc[f+1][2]), "+f"(acc[f+1][3])
                         : "r"(a0), "r"(a1), "r"(a2), "r"(a3), "r"(t2), "r"(t3));
        }
    }

    // ---- fused epilogue: dot with V, reduce, sigmoid ----
    int q = lane & 3, g = lane >> 2;
    int r = mrow_base + g;
    int brow = row0 + r;
    float p0 = 0.f, p1 = 0.f;
#pragma unroll
    for (int f = 0; f < 4; f++) {
        int n = nbase + f * 8 + 2 * q;
        float2 cb = *(const float2*)&g_c[n];
        float2 v0 = *(const float2*)&g_V[(size_t)brow * DD + n];
        float2 v1 = *(const float2*)&g_V[(size_t)(brow + 8) * DD + n];
        p0 += (acc[f][0] + cb.x) * v0.x + (acc[f][1] + cb.y) * v0.y;
        p1 += (acc[f][2] + cb.x) * v1.x + (acc[f][3] + cb.y) * v1.y;
    }
    p0 += __shfl_xor_sync(0xffffffffu, p0, 1);
    p0 += __shfl_xor_sync(0xffffffffu, p0, 2);
    p1 += __shfl_xor_sync(0xffffffffu, p1, 1);
    p1 += __shfl_xor_sync(0xffffffffu, p1, 2);
    if (q == 0) {
        int cg = wid >> 2;
        epi[r][cg]     = p0;
        epi[r + 8][cg] = p1;
    }
    __syncthreads();
    if (tid < 64) {
        float x = epi[tid][0] + epi[tid][1] + epi[tid][2] + epi[tid][3];
        out[row0 + tid] = 1.f / (1.f + expf(-x));
    }
}

// ---------------------------------------------------------------------------
extern "C" void kernel_launch(void* const* d_in, const int* in_sizes, int n_in,
                              void* d_out, int out_size) {
    const int*   neighbors = (const int*)  d_in[0];
    const int*   end_node  = (const int*)  d_in[1];
    const int*   path      = (const int*)  d_in[2];
    const float* emb_start = (const float*)d_in[3];
    const float* emb_end   = (const float*)d_in[4];
    const float* emb_path  = (const float*)d_in[5];
    const float* W1        = (const float*)d_in[6];
    const float* b1        = (const float*)d_in[7];
    const float* W2        = (const float*)d_in[8];
    const float* b2        = (const float*)d_in[9];
    float*       out       = (float*)d_out;

    cudaFuncSetAttribute(k_fused, cudaFuncAttributeMaxDynamicSharedMemorySize,
                         FUSED_SMEM);

    k_prep<<<161, 256>>>(W1, W2, b1, b2, end_node, path, emb_end, emb_path);
    k_fused<<<BB / 64, 512, FUSED_SMEM>>>(neighbors, emb_start, out);
}

// round 9
// speedup vs baseline: 2.6710x; 1.4511x over previous
#include <cuda_runtime.h>
#include <cuda_bf16.h>
#include <math.h>

#define BB   8192
#define EE   4
#define KK   16
#define DD   128
#define AGG_COLS 512          // E*D
#define PREP_BLKS 161         // 32 M-tiles + 1 c + 128 V
#define GATHER_BLKS (BB * EE / 8)   // 4096

// ---------------- scratch (static device globals; no allocation) -------------
__device__ __nv_bfloat16 g_aggh[(size_t)BB * AGG_COLS];  // [B, 512] bf16 means
__device__ float         g_V[(size_t)BB * DD];           // emb_end[end]*sigmoid(emb_path[path])
__device__ __nv_bfloat16 g_Mh[(size_t)AGG_COLS * DD];    // blockdiag(W1)@W2 [512,128] bf16
__device__ float         g_c[DD];                        // b2 + b1-folded bias

__device__ __forceinline__ unsigned s2u(const void* p) {
    return (unsigned)__cvta_generic_to_shared(p);
}

// ---------------------------------------------------------------------------
// k_main: prep blocks first (hidden under the gather stream), then gather.
//   blocks 0..31   : M[e*128+i, j] = sum_k W1[i,k]*W2[e*128+k, j]  (16x128 tile)
//   block  32      : c[j] = b2[j] + sum_m b1[m&127]*W2[m,j]
//   blocks 33..160 : V[b,:] = emb_end[end[b],:] * sigmoid(emb_path[path[b],:])
//   blocks 161+    : gather+mean -> bf16 agg, one warp per (b,e)
__global__ __launch_bounds__(256) void k_main(const int*   __restrict__ nbidx,
                                              const float* __restrict__ emb_start,
                                              const float* __restrict__ W1,
                                              const float* __restrict__ W2,
                                              const float* __restrict__ b1,
                                              const float* __restrict__ b2,
                                              const int*   __restrict__ end_node,
                                              const int*   __restrict__ path,
                                              const float* __restrict__ emb_end,
                                              const float* __restrict__ emb_path) {
    int bid = blockIdx.x;
    int tid = threadIdx.x;

    if (bid >= PREP_BLKS) {
        // ---------------- gather (hot path) ----------------
        int w    = (bid - PREP_BLKS) * 8 + (tid >> 5);   // 0..32767 (b,e) pair
        int lane = tid & 31;

        const int4* ip = (const int4*)(nbidx + (size_t)w * KK);
        int4 id0 = __ldg(ip + 0);
        int4 id1 = __ldg(ip + 1);
        int4 id2 = __ldg(ip + 2);
        int4 id3 = __ldg(ip + 3);

        const float* base = emb_start + lane * 4;
        float4 acc = make_float4(0.f, 0.f, 0.f, 0.f);
#define ACCUM(idx) { const float4 v = *(const float4*)(base + (size_t)(idx) * DD); \
                     acc.x += v.x; acc.y += v.y; acc.z += v.z; acc.w += v.w; }
        ACCUM(id0.x) ACCUM(id0.y) ACCUM(id0.z) ACCUM(id0.w)
        ACCUM(id1.x) ACCUM(id1.y) ACCUM(id1.z) ACCUM(id1.w)
        ACCUM(id2.x) ACCUM(id2.y) ACCUM(id2.z) ACCUM(id2.w)
        ACCUM(id3.x) ACCUM(id3.y) ACCUM(id3.z) ACCUM(id3.w)
#undef ACCUM
        const float inv = 1.f / (float)KK;
        __nv_bfloat162 h0 = __floats2bfloat162_rn(acc.x * inv, acc.y * inv);
        __nv_bfloat162 h1 = __floats2bfloat162_rn(acc.z * inv, acc.w * inv);
        uint2 pk; pk.x = *(unsigned*)&h0; pk.y = *(unsigned*)&h1;
        *(uint2*)(g_aggh + (size_t)w * DD + lane * 4) = pk;  // w*128 == b*512+e*128
        return;
    }

    __shared__ float smA[16][17];
    __shared__ float smB[16][132];
    __shared__ float red[256];

    if (bid < 32) {
        // ---- M tile ----
        int e  = bid >> 3;
        int i0 = (bid & 7) * 16;
        int tx = tid & 15, ty = tid >> 4;
        const float* Bm = W2 + (size_t)e * DD * DD;

        float acc[8];
#pragma unroll
        for (int j = 0; j < 8; j++) acc[j] = 0.f;

        int la_i = tid >> 4, la_k = tid & 15;

        for (int kc = 0; kc < DD; kc += 16) {
            __syncthreads();
            smA[la_k][la_i] = W1[(size_t)(i0 + la_i) * DD + kc + la_k];
#pragma unroll
            for (int it = 0; it < 2; it++) {
                int idx = tid + it * 256;
                int br = idx >> 5, bc = idx & 31;
                *(float4*)&smB[br][bc * 4] =
                    *(const float4*)(Bm + (size_t)(kc + br) * DD + bc * 4);
            }
            __syncthreads();
#pragma unroll
            for (int kk = 0; kk < 16; kk++) {
                float a = smA[kk][ty];
                float4 v0 = *(float4*)&smB[kk][tx * 8];
                float4 v1 = *(float4*)&smB[kk][tx * 8 + 4];
                acc[0] += a * v0.x; acc[1] += a * v0.y;
                acc[2] += a * v0.z; acc[3] += a * v0.w;
                acc[4] += a * v1.x; acc[5] += a * v1.y;
                acc[6] += a * v1.z; acc[7] += a * v1.w;
            }
        }
        int row = e * DD + i0 + ty;
        __nv_bfloat162 h0 = __floats2bfloat162_rn(acc[0], acc[1]);
        __nv_bfloat162 h1 = __floats2bfloat162_rn(acc[2], acc[3]);
        __nv_bfloat162 h2 = __floats2bfloat162_rn(acc[4], acc[5]);
        __nv_bfloat162 h3 = __floats2bfloat162_rn(acc[6], acc[7]);
        uint4 pk;
        pk.x = *(unsigned*)&h0; pk.y = *(unsigned*)&h1;
        pk.z = *(unsigned*)&h2; pk.w = *(unsigned*)&h3;
        *(uint4*)(g_Mh + (size_t)row * DD + tx * 8) = pk;
    } else if (bid == 32) {
        // ---- c ----
        int j = tid & 127, h = tid >> 7;
        float s = (h == 0) ? b2[j] : 0.f;
#pragma unroll 16
        for (int mm = 0; mm < 256; mm++) {
            int m = h * 256 + mm;
            s += b1[m & (DD - 1)] * W2[(size_t)m * DD + j];
        }
        red[tid] = s;
        __syncthreads();
        if (tid < 128) g_c[tid] = red[tid] + red[tid + 128];
    } else {
        // ---- V ----
        int v    = bid - 33;
        int wrp  = v * 8 + (tid >> 5);
        int lane = tid & 31;
#pragma unroll
        for (int i = 0; i < 8; i++) {
            int b  = wrp * 8 + i;
            int en = __ldg(end_node + b);
            int pa = __ldg(path + b);
            float4 ev = *(const float4*)(emb_end  + (size_t)en * DD + lane * 4);
            float4 pv = *(const float4*)(emb_path + (size_t)pa * DD + lane * 4);
            float4 r;
            r.x = ev.x / (1.f + expf(-pv.x));
            r.y = ev.y / (1.f + expf(-pv.y));
            r.z = ev.z / (1.f + expf(-pv.z));
            r.w = ev.w / (1.f + expf(-pv.w));
            *(float4*)(g_V + (size_t)b * DD + lane * 4) = r;
        }
    }
}

// ---------------------------------------------------------------------------
// Tensor-core GEMM + epilogue. 128 CTAs x 512 threads (16 warps: 4 row-groups
// x 4 col-groups). A (64x512) and M (512x128) both bulk-loaded to smem first.
#define B_LD  136
#define A_LD  520
#define BS_ELEMS (AGG_COLS * B_LD)              // 69632 bf16
#define AS_ELEMS (64 * A_LD)                    // 33280 bf16
#define GEMM_SMEM ((BS_ELEMS + AS_ELEMS) * 2 + 64 * 4 * 4)  // ~206.8 KB

__global__ __launch_bounds__(512) void k_gemm2(float* __restrict__ out) {
    extern __shared__ char sm_raw[];
    __nv_bfloat16* Bs = (__nv_bfloat16*)sm_raw;
    __nv_bfloat16* As = Bs + BS_ELEMS;
    float (*epi)[4]   = (float (*)[4])(As + AS_ELEMS);

    int tid  = threadIdx.x;
    int wid  = tid >> 5;
    int lane = tid & 31;
    int row0 = blockIdx.x * 64;

    // ---- bulk load M (8192 uint4) and A (4096 uint4) ----
    {
        const uint4* srcB = (const uint4*)g_Mh;
        const uint4* srcA = (const uint4*)(g_aggh + (size_t)row0 * AGG_COLS);
#pragma unroll
        for (int it = 0; it < 16; it++) {
            int idx = tid + it * 512;            // 0..8191
            int r = idx >> 4, seg = idx & 15;
            *(uint4*)(Bs + r * B_LD + seg * 8) = srcB[idx];
        }
#pragma unroll
        for (int it = 0; it < 8; it++) {
            int idx = tid + it * 512;            // 0..4095
            int r = idx >> 6, seg = idx & 63;    // 64 uint4 per A row
            *(uint4*)(As + r * A_LD + seg * 8) = srcA[idx];
        }
    }
    __syncthreads();

    // ---- GEMM: C[64x128] = A[64x512] @ M[512x128] ----
    int mrow_base = 16 * (wid & 3);
    int nbase     = (wid >> 2) * 32;
    int li = lane & 7, lq = lane >> 3;
    int a_row = mrow_base + li + ((lq & 1) << 3);
    int a_kof = (lq >> 1) << 3;
    int b_kof = li + ((lq & 1) << 3);
    int b_nof = nbase + ((lq >> 1) << 3);

    float acc[4][4];
#pragma unroll
    for (int f = 0; f < 4; f++)
#pragma unroll
        for (int j = 0; j < 4; j++) acc[f][j] = 0.f;

#pragma unroll 4
    for (int ks = 0; ks < 32; ks++) {
        int k = ks * 16;
        unsigned a0, a1, a2, a3;
        unsigned aaddr = s2u(As + a_row * A_LD + k + a_kof);
        asm volatile("ldmatrix.sync.aligned.m8n8.x4.shared.b16 {%0,%1,%2,%3}, [%4];"
                     : "=r"(a0), "=r"(a1), "=r"(a2), "=r"(a3) : "r"(aaddr));
#pragma unroll
        for (int f2 = 0; f2 < 2; f2++) {
            unsigned t0, t1, t2, t3;
            unsigned baddr = s2u(Bs + (k + b_kof) * B_LD + b_nof + f2 * 16);
            asm volatile("ldmatrix.sync.aligned.m8n8.x4.trans.shared.b16 {%0,%1,%2,%3}, [%4];"
                         : "=r"(t0), "=r"(t1), "=r"(t2), "=r"(t3) : "r"(baddr));
            int f = f2 * 2;
            asm volatile("mma.sync.aligned.m16n8k16.row.col.f32.bf16.bf16.f32 "
                         "{%0,%1,%2,%3}, {%4,%5,%6,%7}, {%8,%9}, {%0,%1,%2,%3};"
                         : "+f"(acc[f][0]), "+f"(acc[f][1]), "+f"(acc[f][2]), "+f"(acc[f][3])
                         : "r"(a0), "r"(a1), "r"(a2), "r"(a3), "r"(t0), "r"(t1));
            asm volatile("mma.sync.aligned.m16n8k16.row.col.f32.bf16.bf16.f32 "
                         "{%0,%1,%2,%3}, {%4,%5,%6,%7}, {%8,%9}, {%0,%1,%2,%3};"
                         : "+f"(acc[f+1][0]), "+f"(acc[f+1][1]), "+f"(acc[f+1][2]), "+f"(acc[f+1][3])
                         : "r"(a0), "r"(a1), "r"(a2), "r"(a3), "r"(t2), "r"(t3));
        }
    }

    // ---- fused epilogue: dot with V, reduce, sigmoid ----
    int q = lane & 3, g = lane >> 2;
    int r = mrow_base + g;
    int brow = row0 + r;
    float p0 = 0.f, p1 = 0.f;
#pragma unroll
    for (int f = 0; f < 4; f++) {
        int n = nbase + f * 8 + 2 * q;
        float2 cb = *(const float2*)&g_c[n];
        float2 v0 = *(const float2*)&g_V[(size_t)brow * DD + n];
        float2 v1 = *(const float2*)&g_V[(size_t)(brow + 8) * DD + n];
        p0 += (acc[f][0] + cb.x) * v0.x + (acc[f][1] + cb.y) * v0.y;
        p1 += (acc[f][2] + cb.x) * v1.x + (acc[f][3] + cb.y) * v1.y;
    }
    p0 += __shfl_xor_sync(0xffffffffu, p0, 1);
    p0 += __shfl_xor_sync(0xffffffffu, p0, 2);
    p1 += __shfl_xor_sync(0xffffffffu, p1, 1);
    p1 += __shfl_xor_sync(0xffffffffu, p1, 2);
    if (q == 0) {
        int cg = wid >> 2;
        epi[r][cg]     = p0;
        epi[r + 8][cg] = p1;
    }
    __syncthreads();
    if (tid < 64) {
        float x = epi[tid][0] + epi[tid][1] + epi[tid][2] + epi[tid][3];
        out[row0 + tid] = 1.f / (1.f + expf(-x));
    }
}

// ---------------------------------------------------------------------------
extern "C" void kernel_launch(void* const* d_in, const int* in_sizes, int n_in,
                              void* d_out, int out_size) {
    const int*   neighbors = (const int*)  d_in[0];
    const int*   end_node  = (const int*)  d_in[1];
    const int*   path      = (const int*)  d_in[2];
    const float* emb_start = (const float*)d_in[3];
    const float* emb_end   = (const float*)d_in[4];
    const float* emb_path  = (const float*)d_in[5];
    const float* W1        = (const float*)d_in[6];
    const float* b1        = (const float*)d_in[7];
    const float* W2        = (const float*)d_in[8];
    const float* b2        = (const float*)d_in[9];
    float*       out       = (float*)d_out;

    cudaFuncSetAttribute(k_gemm2, cudaFuncAttributeMaxDynamicSharedMemorySize,
                         GEMM_SMEM);

    k_main<<<PREP_BLKS + GATHER_BLKS, 256>>>(neighbors, emb_start, W1, W2, b1, b2,
                                             end_node, path, emb_end, emb_path);
    k_gemm2<<<BB / 64, 512, GEMM_SMEM>>>(out);
}

// round 11
// speedup vs baseline: 2.6821x; 1.0042x over previous
#include <cuda_runtime.h>
#include <cuda_bf16.h>
#include <math.h>

#define BB   8192
#define EE   4
#define KK   16
#define DD   128
#define AGG_COLS 512          // E*D
#define PREP_BLKS 161         // 32 M-tiles + 1 c + 128 V
#define GATHER_BLKS (BB * EE / 8)   // 4096

// ---------------- scratch (static device globals; no allocation) -------------
__device__ __nv_bfloat16 g_aggh[(size_t)BB * AGG_COLS];  // [B, 512] bf16 means
__device__ float         g_V[(size_t)BB * DD];           // emb_end[end]*sigmoid(emb_path[path])
__device__ __nv_bfloat16 g_Mh[(size_t)AGG_COLS * DD];    // blockdiag(W1)@W2 [512,128] bf16
__device__ float         g_c[DD];                        // b2 + b1-folded bias

__device__ __forceinline__ unsigned s2u(const void* p) {
    return (unsigned)__cvta_generic_to_shared(p);
}

// ---------------------------------------------------------------------------
// k_main: prep blocks first (hidden under the gather stream), then gather.
__global__ __launch_bounds__(256) void k_main(const int*   __restrict__ nbidx,
                                              const float* __restrict__ emb_start,
                                              const float* __restrict__ W1,
                                              const float* __restrict__ W2,
                                              const float* __restrict__ b1,
                                              const float* __restrict__ b2,
                                              const int*   __restrict__ end_node,
                                              const int*   __restrict__ path,
                                              const float* __restrict__ emb_end,
                                              const float* __restrict__ emb_path) {
    int bid = blockIdx.x;
    int tid = threadIdx.x;

    if (bid >= PREP_BLKS) {
        // ---------------- gather (hot path) ----------------
        int w    = (bid - PREP_BLKS) * 8 + (tid >> 5);   // 0..32767 (b,e) pair
        int lane = tid & 31;

        const int4* ip = (const int4*)(nbidx + (size_t)w * KK);
        int4 id0 = __ldg(ip + 0);
        int4 id1 = __ldg(ip + 1);
        int4 id2 = __ldg(ip + 2);
        int4 id3 = __ldg(ip + 3);

        const float* base = emb_start + lane * 4;
        float4 acc = make_float4(0.f, 0.f, 0.f, 0.f);
#define ACCUM(idx) { const float4 v = *(const float4*)(base + (size_t)(idx) * DD); \
                     acc.x += v.x; acc.y += v.y; acc.z += v.z; acc.w += v.w; }
        ACCUM(id0.x) ACCUM(id0.y) ACCUM(id0.z) ACCUM(id0.w)
        ACCUM(id1.x) ACCUM(id1.y) ACCUM(id1.z) ACCUM(id1.w)
        ACCUM(id2.x) ACCUM(id2.y) ACCUM(id2.z) ACCUM(id2.w)
        ACCUM(id3.x) ACCUM(id3.y) ACCUM(id3.z) ACCUM(id3.w)
#undef ACCUM
        const float inv = 1.f / (float)KK;
        __nv_bfloat162 h0 = __floats2bfloat162_rn(acc.x * inv, acc.y * inv);
        __nv_bfloat162 h1 = __floats2bfloat162_rn(acc.z * inv, acc.w * inv);
        uint2 pk; pk.x = *(unsigned*)&h0; pk.y = *(unsigned*)&h1;
        *(uint2*)(g_aggh + (size_t)w * DD + lane * 4) = pk;  // w*128 == b*512+e*128
        return;
    }

    __shared__ float smA[16][17];
    __shared__ float smB[16][132];
    __shared__ float red[256];

    if (bid < 32) {
        // ---- M tile ----
        int e  = bid >> 3;
        int i0 = (bid & 7) * 16;
        int tx = tid & 15, ty = tid >> 4;
        const float* Bm = W2 + (size_t)e * DD * DD;

        float acc[8];
#pragma unroll
        for (int j = 0; j < 8; j++) acc[j] = 0.f;

        int la_i = tid >> 4, la_k = tid & 15;

        for (int kc = 0; kc < DD; kc += 16) {
            __syncthreads();
            smA[la_k][la_i] = W1[(size_t)(i0 + la_i) * DD + kc + la_k];
#pragma unroll
            for (int it = 0; it < 2; it++) {
                int idx = tid + it * 256;
                int br = idx >> 5, bc = idx & 31;
                *(float4*)&smB[br][bc * 4] =
                    *(const float4*)(Bm + (size_t)(kc + br) * DD + bc * 4);
            }
            __syncthreads();
#pragma unroll
            for (int kk = 0; kk < 16; kk++) {
                float a = smA[kk][ty];
                float4 v0 = *(float4*)&smB[kk][tx * 8];
                float4 v1 = *(float4*)&smB[kk][tx * 8 + 4];
                acc[0] += a * v0.x; acc[1] += a * v0.y;
                acc[2] += a * v0.z; acc[3] += a * v0.w;
                acc[4] += a * v1.x; acc[5] += a * v1.y;
                acc[6] += a * v1.z; acc[7] += a * v1.w;
            }
        }
        int row = e * DD + i0 + ty;
        __nv_bfloat162 h0 = __floats2bfloat162_rn(acc[0], acc[1]);
        __nv_bfloat162 h1 = __floats2bfloat162_rn(acc[2], acc[3]);
        __nv_bfloat162 h2 = __floats2bfloat162_rn(acc[4], acc[5]);
        __nv_bfloat162 h3 = __floats2bfloat162_rn(acc[6], acc[7]);
        uint4 pk;
        pk.x = *(unsigned*)&h0; pk.y = *(unsigned*)&h1;
        pk.z = *(unsigned*)&h2; pk.w = *(unsigned*)&h3;
        *(uint4*)(g_Mh + (size_t)row * DD + tx * 8) = pk;
    } else if (bid == 32) {
        // ---- c ----
        int j = tid & 127, h = tid >> 7;
        float s = (h == 0) ? b2[j] : 0.f;
#pragma unroll 16
        for (int mm = 0; mm < 256; mm++) {
            int m = h * 256 + mm;
            s += b1[m & (DD - 1)] * W2[(size_t)m * DD + j];
        }
        red[tid] = s;
        __syncthreads();
        if (tid < 128) g_c[tid] = red[tid] + red[tid + 128];
    } else {
        // ---- V ----
        int v    = bid - 33;
        int wrp  = v * 8 + (tid >> 5);
        int lane = tid & 31;
#pragma unroll
        for (int i = 0; i < 8; i++) {
            int b  = wrp * 8 + i;
            int en = __ldg(end_node + b);
            int pa = __ldg(path + b);
            float4 ev = *(const float4*)(emb_end  + (size_t)en * DD + lane * 4);
            float4 pv = *(const float4*)(emb_path + (size_t)pa * DD + lane * 4);
            float4 r;
            r.x = ev.x / (1.f + expf(-pv.x));
            r.y = ev.y / (1.f + expf(-pv.y));
            r.z = ev.z / (1.f + expf(-pv.z));
            r.w = ev.w / (1.f + expf(-pv.w));
            *(float4*)(g_V + (size_t)b * DD + lane * 4) = r;
        }
    }
}

// ---------------------------------------------------------------------------
// Tensor-core GEMM + epilogue, latency-optimized.
// 128 CTAs x 512 threads = 16 warps: 4 row-groups (m16) x 2 col-groups (n64)
// x 2 k-groups (k256). Split-K halves each warp's serial chain; double-buffered
// ldmatrix fragments hide LDSM latency behind MMA issue.
#define B_LD  136
#define A_LD  520
#define BS_ELEMS (AGG_COLS * B_LD)              // 69632 bf16
#define AS_ELEMS (64 * A_LD)                    // 33280 bf16
#define GEMM_SMEM ((BS_ELEMS + AS_ELEMS) * 2 + 64 * 4 * 4)  // ~206.8 KB

__global__ __launch_bounds__(512) void k_gemm2(float* __restrict__ out) {
    extern __shared__ char sm_raw[];
    __nv_bfloat16* Bs = (__nv_bfloat16*)sm_raw;
    __nv_bfloat16* As = Bs + BS_ELEMS;
    float (*epi)[4]   = (float (*)[4])(As + AS_ELEMS);

    int tid  = threadIdx.x;
    int wid  = tid >> 5;
    int lane = tid & 31;
    int row0 = blockIdx.x * 64;

    // ---- bulk load M (8192 uint4) and A (4096 uint4) ----
    {
        const uint4* srcB = (const uint4*)g_Mh;
        const uint4* srcA = (const uint4*)(g_aggh + (size_t)row0 * AGG_COLS);
#pragma unroll
        for (int it = 0; it < 16; it++) {
            int idx = tid + it * 512;            // 0..8191
            int r = idx >> 4, seg = idx & 15;
            *(uint4*)(Bs + r * B_LD + seg * 8) = srcB[idx];
        }
#pragma unroll
        for (int it = 0; it < 8; it++) {
            int idx = tid + it * 512;            // 0..4095
            int r = idx >> 6, seg = idx & 63;    // 64 uint4 per A row
            *(uint4*)(As + r * A_LD + seg * 8) = srcA[idx];
        }
    }
    __syncthreads();

    // ---- warp mapping ----
    int rg = wid & 3;            // row group: rows [rg*16, rg*16+16)
    int cg = (wid >> 2) & 1;     // col group: n base = cg*64
    int kg = wid >> 3;           // k group:  k in [kg*256, kg*256+256)
    int mrow_base = rg * 16;
    int nbase     = cg * 64;
    int kbase     = kg * 256;

    int li = lane & 7, lq = lane >> 3;
    int a_row = mrow_base + li + ((lq & 1) << 3);
    int a_kof = (lq >> 1) << 3;
    int b_kof = li + ((lq & 1) << 3);
    int b_nof = nbase + ((lq >> 1) << 3);

    float acc[8][4];
#pragma unroll
    for (int f = 0; f < 8; f++)
#pragma unroll
        for (int j = 0; j < 4; j++) acc[f][j] = 0.f;

    unsigned Af[2][4], Bf[2][16];

#define LOADK(buf, kk) {                                                        \
        unsigned aaddr = s2u(As + a_row * A_LD + (kk) + a_kof);                 \
        asm volatile("ldmatrix.sync.aligned.m8n8.x4.shared.b16 {%0,%1,%2,%3}, [%4];" \
                     : "=r"(Af[buf][0]), "=r"(Af[buf][1]),                      \
                       "=r"(Af[buf][2]), "=r"(Af[buf][3]) : "r"(aaddr));        \
        _Pragma("unroll")                                                       \
        for (int f2 = 0; f2 < 4; f2++) {                                        \
            unsigned baddr = s2u(Bs + ((kk) + b_kof) * B_LD + b_nof + f2 * 16); \
            asm volatile("ldmatrix.sync.aligned.m8n8.x4.trans.shared.b16 {%0,%1,%2,%3}, [%4];" \
                         : "=r"(Bf[buf][f2*4+0]), "=r"(Bf[buf][f2*4+1]),        \
                           "=r"(Bf[buf][f2*4+2]), "=r"(Bf[buf][f2*4+3])         \
                         : "r"(baddr));                                         \
        }                                                                       \
    }

    LOADK(0, kbase)
#pragma unroll
    for (int ks = 0; ks < 16; ks++) {
        int cur = ks & 1, nxt = cur ^ 1;
        if (ks < 15) LOADK(nxt, kbase + (ks + 1) * 16)
#pragma unroll
        for (int f2 = 0; f2 < 4; f2++) {
            int f = f2 * 2;
            asm volatile("mma.sync.aligned.m16n8k16.row.col.f32.bf16.bf16.f32 "
                         "{%0,%1,%2,%3}, {%4,%5,%6,%7}, {%8,%9}, {%0,%1,%2,%3};"
                         : "+f"(acc[f][0]), "+f"(acc[f][1]), "+f"(acc[f][2]), "+f"(acc[f][3])
                         : "r"(Af[cur][0]), "r"(Af[cur][1]), "r"(Af[cur][2]), "r"(Af[cur][3]),
                           "r"(Bf[cur][f2*4+0]), "r"(Bf[cur][f2*4+1]));
            asm volatile("mma.sync.aligned.m16n8k16.row.col.f32.bf16.bf16.f32 "
                         "{%0,%1,%2,%3}, {%4,%5,%6,%7}, {%8,%9}, {%0,%1,%2,%3};"
                         : "+f"(acc[f+1][0]), "+f"(acc[f+1][1]), "+f"(acc[f+1][2]), "+f"(acc[f+1][3])
                         : "r"(Af[cur][0]), "r"(Af[cur][1]), "r"(Af[cur][2]), "r"(Af[cur][3]),
                           "r"(Bf[cur][f2*4+2]), "r"(Bf[cur][f2*4+3]));
        }
    }
#undef LOADK

    // ---- fused epilogue: dot with V (bias only from kg==0), reduce, sigmoid ----
    int q = lane & 3, g = lane >> 2;
    int r = mrow_base + g;
    int brow = row0 + r;
    float p0 = 0.f, p1 = 0.f;
#pragma unroll
    for (int f = 0; f < 8; f++) {
        int n = nbase + f * 8 + 2 * q;
        float2 cb = *(const float2*)&g_c[n];
        if (kg) { cb.x = 0.f; cb.y = 0.f; }
        float2 v0 = *(const float2*)&g_V[(size_t)brow * DD + n];
        float2 v1 = *(const float2*)&g_V[(size_t)(brow + 8) * DD + n];
        p0 += (acc[f][0] + cb.x) * v0.x + (acc[f][1] + cb.y) * v0.y;
        p1 += (acc[f][2] + cb.x) * v1.x + (acc[f][3] + cb.y) * v1.y;
    }
    p0 += __shfl_xor_sync(0xffffffffu, p0, 1);
    p0 += __shfl_xor_sync(0xffffffffu, p0, 2);
    p1 += __shfl_xor_sync(0xffffffffu, p1, 1);
    p1 += __shfl_xor_sync(0xffffffffu, p1, 2);
    if (q == 0) {
        int s = wid >> 2;                // cg + 2*kg, 0..3
        epi[r][s]     = p0;
        epi[r + 8][s] = p1;
    }
    __syncthreads();
    if (tid < 64) {
        float x = epi[tid][0] + epi[tid][1] + epi[tid][2] + epi[tid][3];
        out[row0 + tid] = 1.f / (1.f + expf(-x));
    }
}

// ---------------------------------------------------------------------------
extern "C" void kernel_launch(void* const* d_in, const int* in_sizes, int n_in,
                              void* d_out, int out_size) {
    const int*   neighbors = (const int*)  d_in[0];
    const int*   end_node  = (const int*)  d_in[1];
    const int*   path      = (const int*)  d_in[2];
    const float* emb_start = (const float*)d_in[3];
    const float* emb_end   = (const float*)d_in[4];
    const float* emb_path  = (const float*)d_in[5];
    const float* W1        = (const float*)d_in[6];
    const float* b1        = (const float*)d_in[7];
    const float* W2        = (const float*)d_in[8];
    const float* b2        = (const float*)d_in[9];
    float*       out       = (float*)d_out;

    cudaFuncSetAttribute(k_gemm2, cudaFuncAttributeMaxDynamicSharedMemorySize,
                         GEMM_SMEM);

    k_main<<<PREP_BLKS + GATHER_BLKS, 256>>>(neighbors, emb_start, W1, W2, b1, b2,
                                             end_node, path, emb_end, emb_path);
    k_gemm2<<<BB / 64, 512, GEMM_SMEM>>>(out);
}

// round 12
// speedup vs baseline: 2.7884x; 1.0396x over previous
#include <cuda_runtime.h>
#include <cuda_bf16.h>
#include <math.h>

#define BB   8192
#define EE   4
#define KK   16
#define DD   128
#define AGG_COLS 512          // E*D
#define PREP_BLKS 161         // 32 M-tiles + 1 c + 128 V
#define GATHER_BLKS (BB * EE / 8)   // 4096

// ---------------- scratch (static device globals; no allocation) -------------
__device__ __align__(256) __nv_bfloat16 g_aggh[(size_t)BB * AGG_COLS]; // [B,512] bf16 means
__device__ __align__(256) __nv_bfloat16 g_Vh[(size_t)BB * DD];         // bf16 emb_end*sigmoid(path)
__device__ __align__(256) __nv_bfloat16 g_Mh[(size_t)AGG_COLS * DD];   // [512,128] bf16
__device__ __align__(256) float         g_c[DD];                       // folded bias

__device__ __forceinline__ unsigned s2u(const void* p) {
    return (unsigned)__cvta_generic_to_shared(p);
}
__device__ __forceinline__ void cpasync16(unsigned saddr, const void* gptr) {
    asm volatile("cp.async.cg.shared.global [%0], [%1], 16;" :: "r"(saddr), "l"(gptr));
}

// ---------------------------------------------------------------------------
// k_main: prep blocks first (hidden under the gather stream), then gather.
__global__ __launch_bounds__(256) void k_main(const int*   __restrict__ nbidx,
                                              const float* __restrict__ emb_start,
                                              const float* __restrict__ W1,
                                              const float* __restrict__ W2,
                                              const float* __restrict__ b1,
                                              const float* __restrict__ b2,
                                              const int*   __restrict__ end_node,
                                              const int*   __restrict__ path,
                                              const float* __restrict__ emb_end,
                                              const float* __restrict__ emb_path) {
    int bid = blockIdx.x;
    int tid = threadIdx.x;

    if (bid >= PREP_BLKS) {
        // ---------------- gather (hot path) ----------------
        int w    = (bid - PREP_BLKS) * 8 + (tid >> 5);   // 0..32767 (b,e) pair
        int lane = tid & 31;

        const int4* ip = (const int4*)(nbidx + (size_t)w * KK);
        int4 id0 = __ldg(ip + 0);
        int4 id1 = __ldg(ip + 1);
        int4 id2 = __ldg(ip + 2);
        int4 id3 = __ldg(ip + 3);

        const float* base = emb_start + lane * 4;
        float4 acc = make_float4(0.f, 0.f, 0.f, 0.f);
#define ACCUM(idx) { const float4 v = *(const float4*)(base + (size_t)(idx) * DD); \
                     acc.x += v.x; acc.y += v.y; acc.z += v.z; acc.w += v.w; }
        ACCUM(id0.x) ACCUM(id0.y) ACCUM(id0.z) ACCUM(id0.w)
        ACCUM(id1.x) ACCUM(id1.y) ACCUM(id1.z) ACCUM(id1.w)
        ACCUM(id2.x) ACCUM(id2.y) ACCUM(id2.z) ACCUM(id2.w)
        ACCUM(id3.x) ACCUM(id3.y) ACCUM(id3.z) ACCUM(id3.w)
#undef ACCUM
        const float inv = 1.f / (float)KK;
        __nv_bfloat162 h0 = __floats2bfloat162_rn(acc.x * inv, acc.y * inv);
        __nv_bfloat162 h1 = __floats2bfloat162_rn(acc.z * inv, acc.w * inv);
        uint2 pk; pk.x = *(unsigned*)&h0; pk.y = *(unsigned*)&h1;
        *(uint2*)(g_aggh + (size_t)w * DD + lane * 4) = pk;  // w*128 == b*512+e*128
        return;
    }

    __shared__ float smA[16][17];
    __shared__ float smB[16][132];
    __shared__ float red[256];

    if (bid < 32) {
        // ---- M tile ----
        int e  = bid >> 3;
        int i0 = (bid & 7) * 16;
        int tx = tid & 15, ty = tid >> 4;
        const float* Bm = W2 + (size_t)e * DD * DD;

        float acc[8];
#pragma unroll
        for (int j = 0; j < 8; j++) acc[j] = 0.f;

        int la_i = tid >> 4, la_k = tid & 15;

        for (int kc = 0; kc < DD; kc += 16) {
            __syncthreads();
            smA[la_k][la_i] = W1[(size_t)(i0 + la_i) * DD + kc + la_k];
#pragma unroll
            for (int it = 0; it < 2; it++) {
                int idx = tid + it * 256;
                int br = idx >> 5, bc = idx & 31;
                *(float4*)&smB[br][bc * 4] =
                    *(const float4*)(Bm + (size_t)(kc + br) * DD + bc * 4);
            }
            __syncthreads();
#pragma unroll
            for (int kk = 0; kk < 16; kk++) {
                float a = smA[kk][ty];
                float4 v0 = *(float4*)&smB[kk][tx * 8];
                float4 v1 = *(float4*)&smB[kk][tx * 8 + 4];
                acc[0] += a * v0.x; acc[1] += a * v0.y;
                acc[2] += a * v0.z; acc[3] += a * v0.w;
                acc[4] += a * v1.x; acc[5] += a * v1.y;
                acc[6] += a * v1.z; acc[7] += a * v1.w;
            }
        }
        int row = e * DD + i0 + ty;
        __nv_bfloat162 h0 = __floats2bfloat162_rn(acc[0], acc[1]);
        __nv_bfloat162 h1 = __floats2bfloat162_rn(acc[2], acc[3]);
        __nv_bfloat162 h2 = __floats2bfloat162_rn(acc[4], acc[5]);
        __nv_bfloat162 h3 = __floats2bfloat162_rn(acc[6], acc[7]);
        uint4 pk;
        pk.x = *(unsigned*)&h0; pk.y = *(unsigned*)&h1;
        pk.z = *(unsigned*)&h2; pk.w = *(unsigned*)&h3;
        *(uint4*)(g_Mh + (size_t)row * DD + tx * 8) = pk;
    } else if (bid == 32) {
        // ---- c ----
        int j = tid & 127, h = tid >> 7;
        float s = (h == 0) ? b2[j] : 0.f;
#pragma unroll 16
        for (int mm = 0; mm < 256; mm++) {
            int m = h * 256 + mm;
            s += b1[m & (DD - 1)] * W2[(size_t)m * DD + j];
        }
        red[tid] = s;
        __syncthreads();
        if (tid < 128) g_c[tid] = red[tid] + red[tid + 128];
    } else {
        // ---- V (bf16 out) ----
        int v    = bid - 33;
        int wrp  = v * 8 + (tid >> 5);
        int lane = tid & 31;
#pragma unroll
        for (int i = 0; i < 8; i++) {
            int b  = wrp * 8 + i;
            int en = __ldg(end_node + b);
            int pa = __ldg(path + b);
            float4 ev = *(const float4*)(emb_end  + (size_t)en * DD + lane * 4);
            float4 pv = *(const float4*)(emb_path + (size_t)pa * DD + lane * 4);
            float4 r;
            r.x = ev.x / (1.f + expf(-pv.x));
            r.y = ev.y / (1.f + expf(-pv.y));
            r.z = ev.z / (1.f + expf(-pv.z));
            r.w = ev.w / (1.f + expf(-pv.w));
            __nv_bfloat162 h0 = __floats2bfloat162_rn(r.x, r.y);
            __nv_bfloat162 h1 = __floats2bfloat162_rn(r.z, r.w);
            uint2 pk; pk.x = *(unsigned*)&h0; pk.y = *(unsigned*)&h1;
            *(uint2*)(g_Vh + (size_t)b * DD + lane * 4) = pk;
        }
    }
}

// ---------------------------------------------------------------------------
// Tensor-core GEMM + epilogue. 128 CTAs x 512 threads = 16 warps:
// 4 row-groups (m16) x 2 col-groups (n64) x 2 k-groups (k256).
// All operands staged to smem via cp.async (no register batching).
#define B_LD  136
#define A_LD  520
#define V_LD  136
#define BS_ELEMS (AGG_COLS * B_LD)              // 69632 bf16
#define AS_ELEMS (64 * A_LD)                    // 33280 bf16
#define VS_ELEMS (64 * V_LD)                    // 8704  bf16
#define CS_BYTES (DD * 4)                       // 512
#define GEMM_SMEM ((BS_ELEMS + AS_ELEMS + VS_ELEMS) * 2 + CS_BYTES + 64 * 4 * 4)

__global__ __launch_bounds__(512) void k_gemm2(float* __restrict__ out) {
    extern __shared__ char sm_raw[];
    __nv_bfloat16* Bs = (__nv_bfloat16*)sm_raw;
    __nv_bfloat16* As = Bs + BS_ELEMS;
    __nv_bfloat16* Vs = As + AS_ELEMS;
    float*         Cs = (float*)(Vs + VS_ELEMS);
    float (*epi)[4]   = (float (*)[4])(Cs + DD);

    int tid  = threadIdx.x;
    int wid  = tid >> 5;
    int lane = tid & 31;
    int row0 = blockIdx.x * 64;

    // ---- stage everything via cp.async: M(8192), A(4096), V(1024), c(32) x 16B ----
    {
        const char* srcB = (const char*)g_Mh;
        const char* srcA = (const char*)(g_aggh + (size_t)row0 * AGG_COLS);
        const char* srcV = (const char*)(g_Vh   + (size_t)row0 * DD);
#pragma unroll
        for (int it = 0; it < 16; it++) {
            int idx = tid + it * 512;            // 0..8191
            int r = idx >> 4, seg = idx & 15;
            cpasync16(s2u(Bs + r * B_LD + seg * 8), srcB + idx * 16);
        }
#pragma unroll
        for (int it = 0; it < 8; it++) {
            int idx = tid + it * 512;            // 0..4095
            int r = idx >> 6, seg = idx & 63;    // 64 x 16B per A row
            cpasync16(s2u(As + r * A_LD + seg * 8), srcA + idx * 16);
        }
#pragma unroll
        for (int it = 0; it < 2; it++) {
            int idx = tid + it * 512;            // 0..1023
            int r = idx >> 4, seg = idx & 15;
            cpasync16(s2u(Vs + r * V_LD + seg * 8), srcV + idx * 16);
        }
        if (tid < 32) cpasync16(s2u((char*)Cs + tid * 16), (const char*)g_c + tid * 16);
        asm volatile("cp.async.commit_group;");
        asm volatile("cp.async.wait_group 0;");
    }
    __syncthreads();

    // ---- warp mapping ----
    int rg = wid & 3;            // row group: rows [rg*16, rg*16+16)
    int cg = (wid >> 2) & 1;     // col group: n base = cg*64
    int kg = wid >> 3;           // k group:  k in [kg*256, kg*256+256)
    int mrow_base = rg * 16;
    int nbase     = cg * 64;
    int kbase     = kg * 256;

    int li = lane & 7, lq = lane >> 3;
    int a_row = mrow_base + li + ((lq & 1) << 3);
    int a_kof = (lq >> 1) << 3;
    int b_kof = li + ((lq & 1) << 3);
    int b_nof = nbase + ((lq >> 1) << 3);

    float acc[8][4];
#pragma unroll
    for (int f = 0; f < 8; f++)
#pragma unroll
        for (int j = 0; j < 4; j++) acc[f][j] = 0.f;

    unsigned Af[2][4], Bf[2][16];

#define LOADK(buf, kk) {                                                        \
        unsigned aaddr = s2u(As + a_row * A_LD + (kk) + a_kof);                 \
        asm volatile("ldmatrix.sync.aligned.m8n8.x4.shared.b16 {%0,%1,%2,%3}, [%4];" \
                     : "=r"(Af[buf][0]), "=r"(Af[buf][1]),                      \
                       "=r"(Af[buf][2]), "=r"(Af[buf][3]) : "r"(aaddr));        \
        _Pragma("unroll")                                                       \
        for (int f2 = 0; f2 < 4; f2++) {                                        \
            unsigned baddr = s2u(Bs + ((kk) + b_kof) * B_LD + b_nof + f2 * 16); \
            asm volatile("ldmatrix.sync.aligned.m8n8.x4.trans.shared.b16 {%0,%1,%2,%3}, [%4];" \
                         : "=r"(Bf[buf][f2*4+0]), "=r"(Bf[buf][f2*4+1]),        \
                           "=r"(Bf[buf][f2*4+2]), "=r"(Bf[buf][f2*4+3])         \
                         : "r"(baddr));                                         \
        }                                                                       \
    }

    LOADK(0, kbase)
#pragma unroll
    for (int ks = 0; ks < 16; ks++) {
        int cur = ks & 1, nxt = cur ^ 1;
        if (ks < 15) LOADK(nxt, kbase + (ks + 1) * 16)
#pragma unroll
        for (int f2 = 0; f2 < 4; f2++) {
            int f = f2 * 2;
            asm volatile("mma.sync.aligned.m16n8k16.row.col.f32.bf16.bf16.f32 "
                         "{%0,%1,%2,%3}, {%4,%5,%6,%7}, {%8,%9}, {%0,%1,%2,%3};"
                         : "+f"(acc[f][0]), "+f"(acc[f][1]), "+f"(acc[f][2]), "+f"(acc[f][3])
                         : "r"(Af[cur][0]), "r"(Af[cur][1]), "r"(Af[cur][2]), "r"(Af[cur][3]),
                           "r"(Bf[cur][f2*4+0]), "r"(Bf[cur][f2*4+1]));
            asm volatile("mma.sync.aligned.m16n8k16.row.col.f32.bf16.bf16.f32 "
                         "{%0,%1,%2,%3}, {%4,%5,%6,%7}, {%8,%9}, {%0,%1,%2,%3};"
                         : "+f"(acc[f+1][0]), "+f"(acc[f+1][1]), "+f"(acc[f+1][2]), "+f"(acc[f+1][3])
                         : "r"(Af[cur][0]), "r"(Af[cur][1]), "r"(Af[cur][2]), "r"(Af[cur][3]),
                           "r"(Bf[cur][f2*4+2]), "r"(Bf[cur][f2*4+3]));
        }
    }
#undef LOADK

    // ---- fused epilogue: dot with V (smem bf16), reduce, sigmoid ----
    int q = lane & 3, g = lane >> 2;
    int r = mrow_base + g;
    float p0 = 0.f, p1 = 0.f;
#pragma unroll
    for (int f = 0; f < 8; f++) {
        int n = nbase + f * 8 + 2 * q;
        float2 cb = *(const float2*)&Cs[n];
        if (kg) { cb.x = 0.f; cb.y = 0.f; }
        __nv_bfloat162 vh0 = *(const __nv_bfloat162*)(Vs + r * V_LD + n);
        __nv_bfloat162 vh1 = *(const __nv_bfloat162*)(Vs + (r + 8) * V_LD + n);
        float2 v0 = __bfloat1622float2(vh0);
        float2 v1 = __bfloat1622float2(vh1);
        p0 += (acc[f][0] + cb.x) * v0.x + (acc[f][1] + cb.y) * v0.y;
        p1 += (acc[f][2] + cb.x) * v1.x + (acc[f][3] + cb.y) * v1.y;
    }
    p0 += __shfl_xor_sync(0xffffffffu, p0, 1);
    p0 += __shfl_xor_sync(0xffffffffu, p0, 2);
    p1 += __shfl_xor_sync(0xffffffffu, p1, 1);
    p1 += __shfl_xor_sync(0xffffffffu, p1, 2);
    if (q == 0) {
        int s = wid >> 2;                // cg + 2*kg, 0..3
        epi[r][s]     = p0;
        epi[r + 8][s] = p1;
    }
    __syncthreads();
    if (tid < 64) {
        float x = epi[tid][0] + epi[tid][1] + epi[tid][2] + epi[tid][3];
        out[row0 + tid] = 1.f / (1.f + expf(-x));
    }
}

// ---------------------------------------------------------------------------
extern "C" void kernel_launch(void* const* d_in, const int* in_sizes, int n_in,
                              void* d_out, int out_size) {
    const int*   neighbors = (const int*)  d_in[0];
    const int*   end_node  = (const int*)  d_in[1];
    const int*   path      = (const int*)  d_in[2];
    const float* emb_start = (const float*)d_in[3];
    const float* emb_end   = (const float*)d_in[4];
    const float* emb_path  = (const float*)d_in[5];
    const float* W1        = (const float*)d_in[6];
    const float* b1        = (const float*)d_in[7];
    const float* W2        = (const float*)d_in[8];
    const float* b2        = (const float*)d_in[9];
    float*       out       = (float*)d_out;

    cudaFuncSetAttribute(k_gemm2, cudaFuncAttributeMaxDynamicSharedMemorySize,
                         GEMM_SMEM);

    k_main<<<PREP_BLKS + GATHER_BLKS, 256>>>(neighbors, emb_start, W1, W2, b1, b2,
                                             end_node, path, emb_end, emb_path);
    k_gemm2<<<BB / 64, 512, GEMM_SMEM>>>(out);
}